// round 13
// baseline (speedup 1.0000x reference)
#include <cuda_runtime.h>
#include <cstddef>

#define FFT_N 8192
#define NT    1024
#define CH    64
#define NQUAD 1024   // B * CH/4 = 64 * 16

// XOR swizzle on float2 index: conflict-free (<=2-way worst case) for all
// access patterns used here.
#define SWZ(a) ((a) ^ (((a) >> 4) & 15))

// Named barrier over one 512-thread half (ids 1 and 2; id 0 = __syncthreads).
#define BARH(half) asm volatile("bar.sync %0, %1;" :: "r"(1 + (half)), "r"(512) : "memory")

__device__ __forceinline__ float2 cmul(float2 a, float2 b) {
    return make_float2(fmaf(a.x, b.x, -a.y * b.y), fmaf(a.x, b.y, a.y * b.x));
}
__device__ __forceinline__ float2 cadd(float2 a, float2 b) { return make_float2(a.x + b.x, a.y + b.y); }
__device__ __forceinline__ float2 csub(float2 a, float2 b) { return make_float2(a.x - b.x, a.y - b.y); }

template<int DIR>
__device__ __forceinline__ void dft4(float2& a, float2& b, float2& c, float2& d) {
    float2 t0 = cadd(a, c), t1 = csub(a, c);
    float2 t2 = cadd(b, d), t3 = csub(b, d);
    a = cadd(t0, t2);
    c = csub(t0, t2);
    if (DIR > 0) {
        b = make_float2(t1.x + t3.y, t1.y - t3.x);
        d = make_float2(t1.x - t3.y, t1.y + t3.x);
    } else {
        b = make_float2(t1.x - t3.y, t1.y + t3.x);
        d = make_float2(t1.x + t3.y, t1.y - t3.x);
    }
}

// In-place DFT16 (two radix-4 levels). Output X[k2+4*k1] lives in slot
// 4*k2+k1; callers permute on store: slot(o) = ((o&3)<<2)|(o>>2).
template<int DIR>
__device__ __forceinline__ void dft16(float2 v[16]) {
    #pragma unroll
    for (int n1 = 0; n1 < 4; n1++)
        dft4<DIR>(v[n1], v[n1 + 4], v[n1 + 8], v[n1 + 12]);
    const float C1 = 0.92387953251128674f;   // cos(2pi/16)
    const float S1 = 0.38268343236508978f;   // sin(2pi/16)
    const float C2 = 0.70710678118654752f;
    const float s  = (DIR > 0) ? 1.0f : -1.0f;
    v[5]  = cmul(v[5],  make_float2( C1, -s * S1));
    v[6]  = cmul(v[6],  make_float2( C2, -s * C2));
    v[7]  = cmul(v[7],  make_float2( S1, -s * C1));
    v[9]  = cmul(v[9],  make_float2( C2, -s * C2));
    v[10] = cmul(v[10], make_float2(0.f, -s      ));
    v[11] = cmul(v[11], make_float2(-C2, -s * C2));
    v[13] = cmul(v[13], make_float2( S1, -s * C1));
    v[14] = cmul(v[14], make_float2(-C2, -s * C2));
    v[15] = cmul(v[15], make_float2(-C1,  s * S1));
    #pragma unroll
    for (int k2 = 0; k2 < 4; k2++)
        dft4<DIR>(v[4 * k2], v[4 * k2 + 1], v[4 * k2 + 2], v[4 * k2 + 3]);
}

// One in-place radix-16 Stockham DIT stage, half-CTA per pair:
// threads [0,512) -> b0, [512,1024) -> b1. One butterfly per thread.
// Internal sync is PER-HALF (named barriers).
template<int S, int DIR>
__device__ __forceinline__ void stage16_pair(float2* __restrict__ b0,
                                             float2* __restrict__ b1,
                                             int tid, bool p0, bool p1) {
    const int  half = tid >> 9;
    const int  j    = tid & 511;
    float2*    buf  = half ? b1 : b0;
    const bool act  = half ? p1 : p0;
    float2 v[16];
    if (act) {
        #pragma unroll
        for (int r = 0; r < 16; r++)
            v[r] = buf[SWZ(j + r * 512)];
        if (S > 1) {
            const int jq = j & (S - 1);
            float ss, cc;
            sincospif((DIR > 0 ? -2.0f : 2.0f) * (float)jq / (16.0f * (float)S), &ss, &cc);
            float2 w1 = make_float2(cc, ss);
            float2 w  = w1;
            #pragma unroll
            for (int r = 1; r < 16; r++) {
                v[r] = cmul(v[r], w);
                if (r < 15) w = cmul(w, w1);
            }
        }
        dft16<DIR>(v);
    }
    BARH(half);
    if (act) {
        const int jq   = j & (S - 1);
        const int base = jq + (j / S) * (S * 16);
        #pragma unroll
        for (int o = 0; o < 16; o++) {
            int slot = ((o & 3) << 2) | (o >> 2);
            buf[SWZ(base + S * o)] = v[slot];
        }
    }
    BARH(half);
}

// Hermitian rebuild for one (ka, kb=(N-ka)%N) pair of one buffer.
// Surrogate channel: amplitude from the packed-FFT unpack, random phase.
// Kept channel: identity spectrum H = X(k), so the IFFT reproduces the
// original series (~1e-7 rel).
__device__ __forceinline__ void rebuild(float2* __restrict__ buf, int ka, int kb,
                                        float2 phA, float2 phB,
                                        bool sA, bool sB) {
    const float TWO_PI = 6.283185307179586476925f;
    const float scale  = 0.25f / (float)FFT_N;
    float2 Za = buf[SWZ(ka)], Zb = buf[SWZ(kb)];
    float ax = Za.x + Zb.x, ay = Za.y - Zb.y;   // 2*X_A(ka)
    float bx = Za.y + Zb.y, by = Zb.x - Za.x;   // 2*X_B(ka)
    float h1x, h1y, h2x, h2y;
    if (sA) {
        float ampA = sqrtf(fmaf(ax, ax, ay * ay)) * scale;
        float sA1, cA1, sA2, cA2;
        __sincosf(TWO_PI * phA.x, &sA1, &cA1);
        __sincosf(TWO_PI * phA.y, &sA2, &cA2);
        h1x = ampA * (cA1 + cA2);  h1y = ampA * (sA1 - sA2);
    } else {
        h1x = ax * (2.0f * scale); h1y = ay * (2.0f * scale);
    }
    if (sB) {
        float ampB = sqrtf(fmaf(bx, bx, by * by)) * scale;
        float sB1, cB1, sB2, cB2;
        __sincosf(TWO_PI * phB.x, &sB1, &cB1);
        __sincosf(TWO_PI * phB.y, &sB2, &cB2);
        h2x = ampB * (cB1 + cB2);  h2y = ampB * (sB1 - sB2);
    } else {
        h2x = bx * (2.0f * scale); h2y = by * (2.0f * scale);
    }
    buf[SWZ(ka)] = make_float2(h1x - h2y, h1y + h2x);
    buf[SWZ(kb)] = make_float2(h1x + h2y, h2x - h1y);
}

__global__ __launch_bounds__(NT, 1)
void surrogate_kernel(const float* __restrict__ wave,
                      const float* __restrict__ phases,
                      const float* __restrict__ mask,
                      float* __restrict__ out) {
    const int tid = threadIdx.x;
    extern __shared__ float2 sm[];
    float2* b0 = sm;            // pair 0: ch c0 + i*ch(c0+1)
    float2* b1 = sm + FFT_N;    // pair 1: ch c0+2 + i*ch(c0+3)

    // Persistent CTA: loop over channel-quads. Averages per-quad duration
    // variance across ~NQUAD/gridDim iterations and kills wave transitions.
    for (int blk = blockIdx.x; blk < NQUAD; blk += gridDim.x) {
        const int b  = blk >> 4;
        const int c0 = (blk & 15) * 4;

        const bool s0 = mask[b * CH + c0]     < 0.5f;
        const bool s1 = mask[b * CH + c0 + 1] < 0.5f;
        const bool s2 = mask[b * CH + c0 + 2] < 0.5f;
        const bool s3 = mask[b * CH + c0 + 3] < 0.5f;
        const bool p0 = s0 | s1;
        const bool p1 = s2 | s3;

        const float4* w4 = (const float4*)(wave   + (size_t)b * FFT_N * CH + c0);
        const float4* p4 = (const float4*)(phases + (size_t)b * FFT_N * CH + c0);
        float4*       o4 = (float4*)      (out    + (size_t)b * FFT_N * CH + c0);

        // Guard smem reuse against warps still in the previous iteration's
        // store pass (cheap: one bar per iteration).
        __syncthreads();

        if (!p0 && !p1) {
            #pragma unroll 4
            for (int t = tid; t < FFT_N; t += NT)
                o4[(size_t)t * 16] = w4[(size_t)t * 16];
            continue;
        }

        // ---- Load: one float4 per time sample -> both buffers -------------
        #pragma unroll
        for (int i = 0; i < FFT_N / NT; i++) {
            int t = tid + i * NT;
            float4 g = w4[(size_t)t * 16];
            b0[SWZ(t)] = make_float2(g.x, g.y);
            b1[SWZ(t)] = make_float2(g.z, g.w);
        }
        __syncthreads();

        // ---- Forward FFT: radix-16 x3 (halves decoupled) + radix-2 ---------
        stage16_pair<1,   1>(b0, b1, tid, p0, p1);
        stage16_pair<16,  1>(b0, b1, tid, p0, p1);
        stage16_pair<256, 1>(b0, b1, tid, p0, p1);
        __syncthreads();

        #pragma unroll
        for (int i = 0; i < FFT_N / 2 / NT; i++) {
            int j = tid + i * NT;
            float ss, cc;
            sincospif(-(float)j / 4096.0f, &ss, &cc);
            float2 w = make_float2(cc, ss);
            if (p0) {
                float2 u0 = b0[SWZ(j)], u1 = cmul(b0[SWZ(j + 4096)], w);
                b0[SWZ(j)] = cadd(u0, u1);  b0[SWZ(j + 4096)] = csub(u0, u1);
            }
            if (p1) {
                float2 u0 = b1[SWZ(j)], u1 = cmul(b1[SWZ(j + 4096)], w);
                b1[SWZ(j)] = cadd(u0, u1);  b1[SWZ(j + 4096)] = csub(u0, u1);
            }
        }
        __syncthreads();

        // ---- Spectrum rebuild: surrogate lanes random phases; kept lanes ---
        // identity spectrum.
        for (int k = tid; k <= FFT_N / 2; k += NT) {
            const int nk = (FFT_N - k) & (FFT_N - 1);
            float4 pk  = p4[(size_t)k  * 16];
            float4 pnk = p4[(size_t)nk * 16];
            if (p0) rebuild(b0, k, nk, make_float2(pk.x, pnk.x), make_float2(pk.y, pnk.y), s0, s1);
            if (p1) rebuild(b1, k, nk, make_float2(pk.z, pnk.z), make_float2(pk.w, pnk.w), s2, s3);
        }
        __syncthreads();

        // ---- Inverse FFT: radix-16 x3 (halves decoupled) --------------------
        stage16_pair<1,   -1>(b0, b1, tid, p0, p1);
        stage16_pair<16,  -1>(b0, b1, tid, p0, p1);
        stage16_pair<256, -1>(b0, b1, tid, p0, p1);
        __syncthreads();

        // ---- Final inverse radix-2 + float4 store ---------------------------
        #pragma unroll
        for (int i = 0; i < FFT_N / 2 / NT; i++) {
            int j = tid + i * NT;
            float ss, cc;
            sincospif((float)j / 4096.0f, &ss, &cc);
            float2 w = make_float2(cc, ss);
            float2 y0, y1, z0, z1;
            if (p0) {
                float2 u0 = b0[SWZ(j)], u1 = cmul(b0[SWZ(j + 4096)], w);
                y0 = cadd(u0, u1);  y1 = csub(u0, u1);
            } else {   // pair fully kept: b0 still holds the originals
                y0 = b0[SWZ(j)];  y1 = b0[SWZ(j + 4096)];
            }
            if (p1) {
                float2 u0 = b1[SWZ(j)], u1 = cmul(b1[SWZ(j + 4096)], w);
                z0 = cadd(u0, u1);  z1 = csub(u0, u1);
            } else {
                z0 = b1[SWZ(j)];  z1 = b1[SWZ(j + 4096)];
            }
            o4[(size_t)j * 16]          = make_float4(y0.x, y0.y, z0.x, z0.y);
            o4[(size_t)(j + 4096) * 16] = make_float4(y1.x, y1.y, z1.x, z1.y);
        }
    }
}

extern "C" void kernel_launch(void* const* d_in, const int* in_sizes, int n_in,
                              void* d_out, int out_size) {
    const float* wave   = (const float*)d_in[0];
    const float* phases = (const float*)d_in[1];
    const float* maskp  = (const float*)d_in[2];
    float* out = (float*)d_out;

    int nsm = 148;
    cudaDeviceGetAttribute(&nsm, cudaDevAttrMultiProcessorCount, 0);
    if (nsm <= 0 || nsm > NQUAD) nsm = 148;

    const int smem = 2 * FFT_N * (int)sizeof(float2);   // 131,072 B
    cudaFuncSetAttribute(surrogate_kernel,
                         cudaFuncAttributeMaxDynamicSharedMemorySize, smem);
    surrogate_kernel<<<nsm, NT, smem>>>(wave, phases, maskp, out);
}

// round 14
// speedup vs baseline: 1.8208x; 1.8208x over previous
#include <cuda_runtime.h>
#include <cstddef>

#define FFT_N 8192
#define NT    1024
#define CH    64

// XOR swizzle on float2 index: conflict-free (<=2-way worst case) for all
// access patterns used here.
#define SWZ(a) ((a) ^ (((a) >> 4) & 15))

// Named barrier over one 512-thread half (ids 1 and 2; id 0 = __syncthreads).
#define BARH(half) asm volatile("bar.sync %0, %1;" :: "r"(1 + (half)), "r"(512) : "memory")

#define PI_OVER_4096 7.66990393942820615e-4f

__device__ __forceinline__ float2 cmul(float2 a, float2 b) {
    return make_float2(fmaf(a.x, b.x, -a.y * b.y), fmaf(a.x, b.y, a.y * b.x));
}
__device__ __forceinline__ float2 cadd(float2 a, float2 b) { return make_float2(a.x + b.x, a.y + b.y); }
__device__ __forceinline__ float2 csub(float2 a, float2 b) { return make_float2(a.x - b.x, a.y - b.y); }

template<int DIR>
__device__ __forceinline__ void dft4(float2& a, float2& b, float2& c, float2& d) {
    float2 t0 = cadd(a, c), t1 = csub(a, c);
    float2 t2 = cadd(b, d), t3 = csub(b, d);
    a = cadd(t0, t2);
    c = csub(t0, t2);
    if (DIR > 0) {
        b = make_float2(t1.x + t3.y, t1.y - t3.x);
        d = make_float2(t1.x - t3.y, t1.y + t3.x);
    } else {
        b = make_float2(t1.x - t3.y, t1.y + t3.x);
        d = make_float2(t1.x + t3.y, t1.y - t3.x);
    }
}

// In-place DFT16 (two radix-4 levels). Output X[k2+4*k1] lives in slot
// 4*k2+k1; callers permute on store: slot(o) = ((o&3)<<2)|(o>>2).
template<int DIR>
__device__ __forceinline__ void dft16(float2 v[16]) {
    #pragma unroll
    for (int n1 = 0; n1 < 4; n1++)
        dft4<DIR>(v[n1], v[n1 + 4], v[n1 + 8], v[n1 + 12]);
    const float C1 = 0.92387953251128674f;   // cos(2pi/16)
    const float S1 = 0.38268343236508978f;   // sin(2pi/16)
    const float C2 = 0.70710678118654752f;
    const float s  = (DIR > 0) ? 1.0f : -1.0f;
    v[5]  = cmul(v[5],  make_float2( C1, -s * S1));
    v[6]  = cmul(v[6],  make_float2( C2, -s * C2));
    v[7]  = cmul(v[7],  make_float2( S1, -s * C1));
    v[9]  = cmul(v[9],  make_float2( C2, -s * C2));
    v[10] = cmul(v[10], make_float2(0.f, -s      ));
    v[11] = cmul(v[11], make_float2(-C2, -s * C2));
    v[13] = cmul(v[13], make_float2( S1, -s * C1));
    v[14] = cmul(v[14], make_float2(-C2, -s * C2));
    v[15] = cmul(v[15], make_float2(-C1,  s * S1));
    #pragma unroll
    for (int k2 = 0; k2 < 4; k2++)
        dft4<DIR>(v[4 * k2], v[4 * k2 + 1], v[4 * k2 + 2], v[4 * k2 + 3]);
}

// One in-place radix-16 Stockham DIT stage, half-CTA per pair:
// threads [0,512) -> b0, [512,1024) -> b1. One butterfly per thread.
// Internal sync is PER-HALF (named barriers).
// Twiddles: w1 via MUFU __sincosf (args < 2pi/16, high accuracy), then a
// depth-compressed product: w8 = ((w1^2)^2)^2; chain covers r=1..7, and
// w^(s+8) = w^s * w8 (serial depth ~9 instead of ~29).
template<int S, int DIR>
__device__ __forceinline__ void stage16_pair(float2* __restrict__ b0,
                                             float2* __restrict__ b1,
                                             int tid, bool p0, bool p1) {
    const int  half = tid >> 9;
    const int  j    = tid & 511;
    float2*    buf  = half ? b1 : b0;
    const bool act  = half ? p1 : p0;
    float2 v[16];
    if (act) {
        #pragma unroll
        for (int r = 0; r < 16; r++)
            v[r] = buf[SWZ(j + r * 512)];
        if (S > 1) {
            const int   jq = j & (S - 1);
            const float K  = (DIR > 0 ? -6.2831853071795865f : 6.2831853071795865f)
                             / (16.0f * (float)S);
            float ss, cc;
            __sincosf(K * (float)jq, &ss, &cc);
            float2 w1 = make_float2(cc, ss);
            float2 w2 = cmul(w1, w1);
            float2 w4 = cmul(w2, w2);
            float2 w8 = cmul(w4, w4);
            v[8] = cmul(v[8], w8);
            float2 w = w1;
            #pragma unroll
            for (int s = 1; s < 8; s++) {
                v[s]     = cmul(v[s], w);
                v[s + 8] = cmul(cmul(v[s + 8], w8), w);
                if (s < 7) w = cmul(w, w1);
            }
        }
        dft16<DIR>(v);
    }
    BARH(half);
    if (act) {
        const int jq   = j & (S - 1);
        const int base = jq + (j / S) * (S * 16);
        #pragma unroll
        for (int o = 0; o < 16; o++) {
            int slot = ((o & 3) << 2) | (o >> 2);
            buf[SWZ(base + S * o)] = v[slot];
        }
    }
    BARH(half);
}

// Hermitian rebuild for one (ka, kb=(N-ka)%N) pair of one buffer.
// Surrogate channel: amplitude from the packed-FFT unpack, random phase.
// Kept channel: identity spectrum H = X(k), so the IFFT reproduces the
// original series (~1e-7 rel).
__device__ __forceinline__ void rebuild(float2* __restrict__ buf, int ka, int kb,
                                        float2 phA, float2 phB,
                                        bool sA, bool sB) {
    const float TWO_PI = 6.283185307179586476925f;
    const float scale  = 0.25f / (float)FFT_N;
    float2 Za = buf[SWZ(ka)], Zb = buf[SWZ(kb)];
    float ax = Za.x + Zb.x, ay = Za.y - Zb.y;   // 2*X_A(ka)
    float bx = Za.y + Zb.y, by = Zb.x - Za.x;   // 2*X_B(ka)
    float h1x, h1y, h2x, h2y;
    if (sA) {
        float ampA = sqrtf(fmaf(ax, ax, ay * ay)) * scale;
        float sA1, cA1, sA2, cA2;
        __sincosf(TWO_PI * phA.x, &sA1, &cA1);
        __sincosf(TWO_PI * phA.y, &sA2, &cA2);
        h1x = ampA * (cA1 + cA2);  h1y = ampA * (sA1 - sA2);
    } else {
        h1x = ax * (2.0f * scale); h1y = ay * (2.0f * scale);
    }
    if (sB) {
        float ampB = sqrtf(fmaf(bx, bx, by * by)) * scale;
        float sB1, cB1, sB2, cB2;
        __sincosf(TWO_PI * phB.x, &sB1, &cB1);
        __sincosf(TWO_PI * phB.y, &sB2, &cB2);
        h2x = ampB * (cB1 + cB2);  h2y = ampB * (sB1 - sB2);
    } else {
        h2x = bx * (2.0f * scale); h2y = by * (2.0f * scale);
    }
    buf[SWZ(ka)] = make_float2(h1x - h2y, h1y + h2x);
    buf[SWZ(kb)] = make_float2(h1x + h2y, h2x - h1y);
}

__global__ __launch_bounds__(NT, 1)
void surrogate_kernel(const float* __restrict__ wave,
                      const float* __restrict__ phases,
                      const float* __restrict__ mask,
                      float* __restrict__ out) {
    const int blk = blockIdx.x;
    const int b   = blk >> 4;
    const int c0  = (blk & 15) * 4;
    const int tid = threadIdx.x;

    const bool s0 = mask[b * CH + c0]     < 0.5f;
    const bool s1 = mask[b * CH + c0 + 1] < 0.5f;
    const bool s2 = mask[b * CH + c0 + 2] < 0.5f;
    const bool s3 = mask[b * CH + c0 + 3] < 0.5f;
    const bool p0 = s0 | s1;
    const bool p1 = s2 | s3;

    const float4* w4 = (const float4*)(wave   + (size_t)b * FFT_N * CH + c0);
    const float4* p4 = (const float4*)(phases + (size_t)b * FFT_N * CH + c0);
    float4*       o4 = (float4*)      (out    + (size_t)b * FFT_N * CH + c0);

    if (!p0 && !p1) {
        #pragma unroll 4
        for (int t = tid; t < FFT_N; t += NT)
            o4[(size_t)t * 16] = w4[(size_t)t * 16];
        return;
    }

    extern __shared__ float2 sm[];
    float2* b0 = sm;            // pair 0: ch c0 + i*ch(c0+1)
    float2* b1 = sm + FFT_N;    // pair 1: ch c0+2 + i*ch(c0+3)

    // ---- Load: one float4 per time sample -> both buffers -----------------
    #pragma unroll
    for (int i = 0; i < FFT_N / NT; i++) {
        int t = tid + i * NT;
        float4 g = w4[(size_t)t * 16];
        b0[SWZ(t)] = make_float2(g.x, g.y);
        b1[SWZ(t)] = make_float2(g.z, g.w);
    }
    __syncthreads();

    // ---- Forward FFT: radix-16 x3 (halves decoupled) + radix-2 -------------
    stage16_pair<1,   1>(b0, b1, tid, p0, p1);
    stage16_pair<16,  1>(b0, b1, tid, p0, p1);
    stage16_pair<256, 1>(b0, b1, tid, p0, p1);
    __syncthreads();

    #pragma unroll
    for (int i = 0; i < FFT_N / 2 / NT; i++) {
        int j = tid + i * NT;
        float ss, cc;
        __sincosf(-(float)j * PI_OVER_4096, &ss, &cc);
        float2 w = make_float2(cc, ss);
        if (p0) {
            float2 u0 = b0[SWZ(j)], u1 = cmul(b0[SWZ(j + 4096)], w);
            b0[SWZ(j)] = cadd(u0, u1);  b0[SWZ(j + 4096)] = csub(u0, u1);
        }
        if (p1) {
            float2 u0 = b1[SWZ(j)], u1 = cmul(b1[SWZ(j + 4096)], w);
            b1[SWZ(j)] = cadd(u0, u1);  b1[SWZ(j + 4096)] = csub(u0, u1);
        }
    }
    __syncthreads();

    // ---- Spectrum rebuild: surrogate lanes random phases; kept lanes -------
    // identity spectrum (IFFT then reproduces the original series).
    for (int k = tid; k <= FFT_N / 2; k += NT) {
        const int nk = (FFT_N - k) & (FFT_N - 1);
        float4 pk  = p4[(size_t)k  * 16];
        float4 pnk = p4[(size_t)nk * 16];
        if (p0) rebuild(b0, k, nk, make_float2(pk.x, pnk.x), make_float2(pk.y, pnk.y), s0, s1);
        if (p1) rebuild(b1, k, nk, make_float2(pk.z, pnk.z), make_float2(pk.w, pnk.w), s2, s3);
    }
    __syncthreads();

    // ---- Inverse FFT: radix-16 x3 (halves decoupled) ------------------------
    stage16_pair<1,   -1>(b0, b1, tid, p0, p1);
    stage16_pair<16,  -1>(b0, b1, tid, p0, p1);
    stage16_pair<256, -1>(b0, b1, tid, p0, p1);
    __syncthreads();

    // ---- Final inverse radix-2 + float4 store (no reload, no select) -------
    #pragma unroll
    for (int i = 0; i < FFT_N / 2 / NT; i++) {
        int j = tid + i * NT;
        float ss, cc;
        __sincosf((float)j * PI_OVER_4096, &ss, &cc);
        float2 w = make_float2(cc, ss);
        float2 y0, y1, z0, z1;
        if (p0) {
            float2 u0 = b0[SWZ(j)], u1 = cmul(b0[SWZ(j + 4096)], w);
            y0 = cadd(u0, u1);  y1 = csub(u0, u1);
        } else {   // pair fully kept: b0 still holds the originals (in place)
            y0 = b0[SWZ(j)];  y1 = b0[SWZ(j + 4096)];
        }
        if (p1) {
            float2 u0 = b1[SWZ(j)], u1 = cmul(b1[SWZ(j + 4096)], w);
            z0 = cadd(u0, u1);  z1 = csub(u0, u1);
        } else {
            z0 = b1[SWZ(j)];  z1 = b1[SWZ(j + 4096)];
        }
        o4[(size_t)j * 16]          = make_float4(y0.x, y0.y, z0.x, z0.y);
        o4[(size_t)(j + 4096) * 16] = make_float4(y1.x, y1.y, z1.x, z1.y);
    }
}

extern "C" void kernel_launch(void* const* d_in, const int* in_sizes, int n_in,
                              void* d_out, int out_size) {
    const float* wave   = (const float*)d_in[0];
    const float* phases = (const float*)d_in[1];
    const float* maskp  = (const float*)d_in[2];
    float* out = (float*)d_out;

    const int B = in_sizes[0] / (FFT_N * CH);
    const int smem = 2 * FFT_N * (int)sizeof(float2);   // 131,072 B

    cudaFuncSetAttribute(surrogate_kernel,
                         cudaFuncAttributeMaxDynamicSharedMemorySize, smem);
    surrogate_kernel<<<B * (CH / 4), NT, smem>>>(wave, phases, maskp, out);
}

// round 15
// speedup vs baseline: 1.8500x; 1.0160x over previous
#include <cuda_runtime.h>
#include <cstddef>

#define FFT_N 8192
#define NT    1024
#define CH    64

// XOR swizzle on float2 index: conflict-free (<=2-way worst case) for all
// access patterns used here.
#define SWZ(a) ((a) ^ (((a) >> 4) & 15))

// Named barrier over one 512-thread half (ids 1 and 2; id 0 = __syncthreads).
#define BARH(half) asm volatile("bar.sync %0, %1;" :: "r"(1 + (half)), "r"(512) : "memory")

#define PI_OVER_4096 7.66990393942820615e-4f

__device__ __forceinline__ float2 cmul(float2 a, float2 b) {
    return make_float2(fmaf(a.x, b.x, -a.y * b.y), fmaf(a.x, b.y, a.y * b.x));
}
__device__ __forceinline__ float2 cadd(float2 a, float2 b) { return make_float2(a.x + b.x, a.y + b.y); }
__device__ __forceinline__ float2 csub(float2 a, float2 b) { return make_float2(a.x - b.x, a.y - b.y); }

template<int DIR>
__device__ __forceinline__ void dft4(float2& a, float2& b, float2& c, float2& d) {
    float2 t0 = cadd(a, c), t1 = csub(a, c);
    float2 t2 = cadd(b, d), t3 = csub(b, d);
    a = cadd(t0, t2);
    c = csub(t0, t2);
    if (DIR > 0) {
        b = make_float2(t1.x + t3.y, t1.y - t3.x);
        d = make_float2(t1.x - t3.y, t1.y + t3.x);
    } else {
        b = make_float2(t1.x - t3.y, t1.y + t3.x);
        d = make_float2(t1.x + t3.y, t1.y - t3.x);
    }
}

// In-place DFT16 (two radix-4 levels). Output X[k2+4*k1] lives in slot
// 4*k2+k1; callers permute on store: slot(o) = ((o&3)<<2)|(o>>2).
template<int DIR>
__device__ __forceinline__ void dft16(float2 v[16]) {
    #pragma unroll
    for (int n1 = 0; n1 < 4; n1++)
        dft4<DIR>(v[n1], v[n1 + 4], v[n1 + 8], v[n1 + 12]);
    const float C1 = 0.92387953251128674f;   // cos(2pi/16)
    const float S1 = 0.38268343236508978f;   // sin(2pi/16)
    const float C2 = 0.70710678118654752f;
    const float s  = (DIR > 0) ? 1.0f : -1.0f;
    v[5]  = cmul(v[5],  make_float2( C1, -s * S1));
    v[6]  = cmul(v[6],  make_float2( C2, -s * C2));
    v[7]  = cmul(v[7],  make_float2( S1, -s * C1));
    v[9]  = cmul(v[9],  make_float2( C2, -s * C2));
    v[10] = cmul(v[10], make_float2(0.f, -s      ));
    v[11] = cmul(v[11], make_float2(-C2, -s * C2));
    v[13] = cmul(v[13], make_float2( S1, -s * C1));
    v[14] = cmul(v[14], make_float2(-C2, -s * C2));
    v[15] = cmul(v[15], make_float2(-C1,  s * S1));
    #pragma unroll
    for (int k2 = 0; k2 < 4; k2++)
        dft4<DIR>(v[4 * k2], v[4 * k2 + 1], v[4 * k2 + 2], v[4 * k2 + 3]);
}

// One in-place radix-16 Stockham DIT stage, half-CTA per pair:
// threads [0,512) -> b0, [512,1024) -> b1. One butterfly per thread.
// Internal sync is PER-HALF (named barriers).
// Twiddles: w1 via MUFU __sincosf, depth-compressed product chain.
template<int S, int DIR>
__device__ __forceinline__ void stage16_pair(float2* __restrict__ b0,
                                             float2* __restrict__ b1,
                                             int tid, bool p0, bool p1) {
    const int  half = tid >> 9;
    const int  j    = tid & 511;
    float2*    buf  = half ? b1 : b0;
    const bool act  = half ? p1 : p0;
    float2 v[16];
    if (act) {
        #pragma unroll
        for (int r = 0; r < 16; r++)
            v[r] = buf[SWZ(j + r * 512)];
        if (S > 1) {
            const int   jq = j & (S - 1);
            const float K  = (DIR > 0 ? -6.2831853071795865f : 6.2831853071795865f)
                             / (16.0f * (float)S);
            float ss, cc;
            __sincosf(K * (float)jq, &ss, &cc);
            float2 w1 = make_float2(cc, ss);
            float2 w2 = cmul(w1, w1);
            float2 w4 = cmul(w2, w2);
            float2 w8 = cmul(w4, w4);
            v[8] = cmul(v[8], w8);
            float2 w = w1;
            #pragma unroll
            for (int s = 1; s < 8; s++) {
                v[s]     = cmul(v[s], w);
                v[s + 8] = cmul(cmul(v[s + 8], w8), w);
                if (s < 7) w = cmul(w, w1);
            }
        }
        dft16<DIR>(v);
    }
    BARH(half);
    if (act) {
        const int jq   = j & (S - 1);
        const int base = jq + (j / S) * (S * 16);
        #pragma unroll
        for (int o = 0; o < 16; o++) {
            int slot = ((o & 3) << 2) | (o >> 2);
            buf[SWZ(base + S * o)] = v[slot];
        }
    }
    BARH(half);
}

// Hermitian rebuild for one (ka, kb=(N-ka)%N) pair of one buffer.
// Surrogate channel: amplitude from the packed-FFT unpack, random phase.
// Kept channel: identity spectrum H = X(k) -> IFFT reproduces the original.
__device__ __forceinline__ void rebuild(float2* __restrict__ buf, int ka, int kb,
                                        float2 phA, float2 phB,
                                        bool sA, bool sB) {
    const float TWO_PI = 6.283185307179586476925f;
    const float scale  = 0.25f / (float)FFT_N;
    float2 Za = buf[SWZ(ka)], Zb = buf[SWZ(kb)];
    float ax = Za.x + Zb.x, ay = Za.y - Zb.y;   // 2*X_A(ka)
    float bx = Za.y + Zb.y, by = Zb.x - Za.x;   // 2*X_B(ka)
    float h1x, h1y, h2x, h2y;
    if (sA) {
        float ampA = sqrtf(fmaf(ax, ax, ay * ay)) * scale;
        float sA1, cA1, sA2, cA2;
        __sincosf(TWO_PI * phA.x, &sA1, &cA1);
        __sincosf(TWO_PI * phA.y, &sA2, &cA2);
        h1x = ampA * (cA1 + cA2);  h1y = ampA * (sA1 - sA2);
    } else {
        h1x = ax * (2.0f * scale); h1y = ay * (2.0f * scale);
    }
    if (sB) {
        float ampB = sqrtf(fmaf(bx, bx, by * by)) * scale;
        float sB1, cB1, sB2, cB2;
        __sincosf(TWO_PI * phB.x, &sB1, &cB1);
        __sincosf(TWO_PI * phB.y, &sB2, &cB2);
        h2x = ampB * (cB1 + cB2);  h2y = ampB * (sB1 - sB2);
    } else {
        h2x = bx * (2.0f * scale); h2y = by * (2.0f * scale);
    }
    buf[SWZ(ka)] = make_float2(h1x - h2y, h1y + h2x);
    buf[SWZ(kb)] = make_float2(h1x + h2y, h2x - h1y);
}

__global__ __launch_bounds__(NT, 1)
void surrogate_kernel(const float* __restrict__ wave,
                      const float* __restrict__ phases,
                      const float* __restrict__ mask,
                      float* __restrict__ out) {
    const int blk = blockIdx.x;
    const int b   = blk >> 4;
    const int c0  = (blk & 15) * 4;
    const int tid = threadIdx.x;

    const bool s0 = mask[b * CH + c0]     < 0.5f;
    const bool s1 = mask[b * CH + c0 + 1] < 0.5f;
    const bool s2 = mask[b * CH + c0 + 2] < 0.5f;
    const bool s3 = mask[b * CH + c0 + 3] < 0.5f;
    const bool p0 = s0 | s1;
    const bool p1 = s2 | s3;

    const float4* w4 = (const float4*)(wave   + (size_t)b * FFT_N * CH + c0);
    const float4* p4 = (const float4*)(phases + (size_t)b * FFT_N * CH + c0);
    float4*       o4 = (float4*)      (out    + (size_t)b * FFT_N * CH + c0);

    if (!p0 && !p1) {
        #pragma unroll 4
        for (int t = tid; t < FFT_N; t += NT)
            o4[(size_t)t * 16] = w4[(size_t)t * 16];
        return;
    }

    extern __shared__ float2 sm[];
    float2* b0 = sm;            // pair 0: ch c0 + i*ch(c0+1)
    float2* b1 = sm + FFT_N;    // pair 1: ch c0+2 + i*ch(c0+3)

    // ---- Fused load + forward radix-2 (S=1: twiddle-free) ------------------
    // Active pairs get the first Stockham stage for free; kept pairs store
    // the raw series (identity layout) so the final fast path sees originals.
    #pragma unroll
    for (int i = 0; i < FFT_N / 2 / NT; i++) {
        int t = tid + i * NT;   // [0, 4096)
        float4 ga = w4[(size_t)t * 16];
        float4 gb = w4[(size_t)(t + 4096) * 16];
        if (p0) {
            b0[SWZ(2 * t)]     = make_float2(ga.x + gb.x, ga.y + gb.y);
            b0[SWZ(2 * t + 1)] = make_float2(ga.x - gb.x, ga.y - gb.y);
        } else {
            b0[SWZ(t)]         = make_float2(ga.x, ga.y);
            b0[SWZ(t + 4096)]  = make_float2(gb.x, gb.y);
        }
        if (p1) {
            b1[SWZ(2 * t)]     = make_float2(ga.z + gb.z, ga.w + gb.w);
            b1[SWZ(2 * t + 1)] = make_float2(ga.z - gb.z, ga.w - gb.w);
        } else {
            b1[SWZ(t)]         = make_float2(ga.z, ga.w);
            b1[SWZ(t + 4096)]  = make_float2(gb.z, gb.w);
        }
    }
    __syncthreads();

    // ---- Forward FFT: radix-16 at S=2, 32, 512 (halves decoupled) ----------
    stage16_pair<2,   1>(b0, b1, tid, p0, p1);
    stage16_pair<32,  1>(b0, b1, tid, p0, p1);
    stage16_pair<512, 1>(b0, b1, tid, p0, p1);
    __syncthreads();

    // ---- Spectrum rebuild (fixed-trip, unrolled for load batching) ---------
    #pragma unroll
    for (int i = 0; i < 4; i++) {
        const int k  = tid + i * NT;                 // [0, 4096)
        const int nk = (FFT_N - k) & (FFT_N - 1);
        float4 pk  = p4[(size_t)k  * 16];
        float4 pnk = p4[(size_t)nk * 16];
        if (p0) rebuild(b0, k, nk, make_float2(pk.x, pnk.x), make_float2(pk.y, pnk.y), s0, s1);
        if (p1) rebuild(b1, k, nk, make_float2(pk.z, pnk.z), make_float2(pk.w, pnk.w), s2, s3);
    }
    if (tid == 0) {                                   // k = 4096 (self-paired)
        float4 pk = p4[(size_t)4096 * 16];
        if (p0) rebuild(b0, 4096, 4096, make_float2(pk.x, pk.x), make_float2(pk.y, pk.y), s0, s1);
        if (p1) rebuild(b1, 4096, 4096, make_float2(pk.z, pk.z), make_float2(pk.w, pk.w), s2, s3);
    }
    __syncthreads();

    // ---- Inverse FFT: radix-16 x3 (halves decoupled) ------------------------
    stage16_pair<1,   -1>(b0, b1, tid, p0, p1);
    stage16_pair<16,  -1>(b0, b1, tid, p0, p1);
    stage16_pair<256, -1>(b0, b1, tid, p0, p1);
    __syncthreads();

    // ---- Final inverse radix-2 + float4 store (no reload, no select) -------
    #pragma unroll
    for (int i = 0; i < FFT_N / 2 / NT; i++) {
        int j = tid + i * NT;
        float ss, cc;
        __sincosf((float)j * PI_OVER_4096, &ss, &cc);
        float2 w = make_float2(cc, ss);
        float2 y0, y1, z0, z1;
        if (p0) {
            float2 u0 = b0[SWZ(j)], u1 = cmul(b0[SWZ(j + 4096)], w);
            y0 = cadd(u0, u1);  y1 = csub(u0, u1);
        } else {   // pair fully kept: b0 holds the originals (identity layout)
            y0 = b0[SWZ(j)];  y1 = b0[SWZ(j + 4096)];
        }
        if (p1) {
            float2 u0 = b1[SWZ(j)], u1 = cmul(b1[SWZ(j + 4096)], w);
            z0 = cadd(u0, u1);  z1 = csub(u0, u1);
        } else {
            z0 = b1[SWZ(j)];  z1 = b1[SWZ(j + 4096)];
        }
        o4[(size_t)j * 16]          = make_float4(y0.x, y0.y, z0.x, z0.y);
        o4[(size_t)(j + 4096) * 16] = make_float4(y1.x, y1.y, z1.x, z1.y);
    }
}

extern "C" void kernel_launch(void* const* d_in, const int* in_sizes, int n_in,
                              void* d_out, int out_size) {
    const float* wave   = (const float*)d_in[0];
    const float* phases = (const float*)d_in[1];
    const float* maskp  = (const float*)d_in[2];
    float* out = (float*)d_out;

    const int B = in_sizes[0] / (FFT_N * CH);
    const int smem = 2 * FFT_N * (int)sizeof(float2);   // 131,072 B

    cudaFuncSetAttribute(surrogate_kernel,
                         cudaFuncAttributeMaxDynamicSharedMemorySize, smem);
    surrogate_kernel<<<B * (CH / 4), NT, smem>>>(wave, phases, maskp, out);
}